// round 14
// baseline (speedup 1.0000x reference)
#include <cuda_runtime.h>
#include <cstdint>

// WinCorr: corr[b,off,z,y,x] = (1/8) * sum_c x[b,c,z,y,x] * y[b,c,z+dz-1,y+dy-1,x+dx-1]
// x,y = (2,64,80,80,80) f32 ; out = (2,27,80,80,80) f32
// R14: R13 (tile 4x8x8, TX=2, 128 thr, 27 offs/thread, 16B-chunk staging, 6 CTAs/SM)
//      with the invalid-slot zero-fill race fixed (explicit predicate on slot 1).

#define B_  2
#define C_  64
#define D_  80
#define H_  80
#define W_  80

#define TZ  4
#define TY  8
#define TXB 8
#define TX  2
#define NTH 128

#define SMZ 6
#define SMY 10
#define SMXW 24          // row stride (words)
#define STAGES 3
#define BUFBYTES (SMZ*SMY*SMXW*4)   // 5760 ; x3 = 17280
#define HSBYTES  256                 // 64-entry left-halo col per stage
#define NROWS (SMZ*SMY)              // 60
#define NSLOTS (NROWS*4)             // 240: 2x16B + right col + left halo per row

typedef unsigned long long u64;

__device__ __forceinline__ uint32_t smem_u32(const void* p) {
    return (uint32_t)__cvta_generic_to_shared(p);
}
__device__ __forceinline__ void cp_async16(uint32_t saddr, const void* gaddr, uint32_t srcsz) {
    asm volatile("cp.async.cg.shared.global [%0], [%1], 16, %2;\n"
                 :: "r"(saddr), "l"(gaddr), "r"(srcsz) : "memory");
}
__device__ __forceinline__ void cp_async4(uint32_t saddr, const void* gaddr, uint32_t srcsz) {
    asm volatile("cp.async.ca.shared.global [%0], [%1], 4, %2;\n"
                 :: "r"(saddr), "l"(gaddr), "r"(srcsz) : "memory");
}
__device__ __forceinline__ void cp_commit() {
    asm volatile("cp.async.commit_group;\n" ::: "memory");
}
template<int N> __device__ __forceinline__ void cp_wait() {
    asm volatile("cp.async.wait_group %0;\n" :: "n"(N) : "memory");
}
__device__ __forceinline__ void ffma2(u64& acc, u64 a, u64 b) {
    asm("fma.rn.f32x2 %0, %1, %2, %0;" : "+l"(acc) : "l"(a), "l"(b));
}
__device__ __forceinline__ u64 packf2(float lo, float hi) {
    u64 r; asm("mov.b64 %0, {%1, %2};" : "=l"(r) : "f"(lo), "f"(hi)); return r;
}
__device__ __forceinline__ float2 unpackf2(u64 v) {
    float2 r; asm("mov.b64 {%0, %1}, %2;" : "=f"(r.x), "=f"(r.y) : "l"(v)); return r;
}

__global__ void __launch_bounds__(NTH, 6)
wincorr_kernel(const float* __restrict__ x,
               const float* __restrict__ y,
               float* __restrict__ out)
{
    // ---- decode block -> (b, z0, y0, x0) ----
    int bid = blockIdx.x;
    int bx = bid % (W_ / TXB); bid /= (W_ / TXB);   // 10
    int by = bid % (H_ / TY);  bid /= (H_ / TY);    // 10
    int bz = bid % (D_ / TZ);  bid /= (D_ / TZ);    // 20
    int b  = bid;
    const int z0 = bz * TZ, y0 = by * TY, x0 = bx * TXB;

    const int tid = threadIdx.x;
    const int tx = tid & 3;
    const int ty = (tid >> 2) & 7;
    const int tz = tid >> 5;

    // sm word w <-> gmem col x0+w (w=0..8 used); left halo (x0-1) in hs
    __shared__ __align__(16) float sm[STAGES][SMZ][SMY][SMXW];
    __shared__ __align__(16) float hs[STAGES][64];

    const int plane = H_ * W_;       // 6400
    const int vol   = D_ * plane;    // 512000
    const uint32_t volbytes = (uint32_t)vol * 4u;

    const float* xb = x + (size_t)b * C_ * vol;
    const float* yb = y + (size_t)b * C_ * vol;
    const char*  ybc = (const char*)yb;

    // ---- two staging slots per thread: s = tid, tid+128 (same k = s&3) ----
    const int k = tid & 3;               // 0,1: 16B chunk; 2: right col; 3: left halo
    const bool is16 = (k < 2);
    const bool isMain = (k < 3);
    const bool v1 = (tid < NSLOTS - NTH);   // slot 1 validity (slot 0 always valid)
    uint32_t sadr0, sadr1, goff0, goff1, csz0, csz1;
    {
#pragma unroll
        for (int sl = 0; sl < 2; sl++) {
            int s = tid + sl * NTH;
            bool v = (s < NSLOTS);
            int ss = v ? s : 0;
            int r = ss >> 2;
            int lz = r / SMY;
            int ly = r - lz * SMY;
            int gz = z0 - 1 + lz, gy = y0 - 1 + ly;
            bool rowok = v && ((unsigned)gz < (unsigned)D_) && ((unsigned)gy < (unsigned)H_);
            int cz = min(max(gz, 0), D_ - 1);
            int cy = min(max(gy, 0), H_ - 1);
            int rowbase = cz * plane + cy * W_;
            uint32_t go, cs, sa;
            if (k < 2) {                         // 16B chunk at x0+4k -> words 4k..4k+3
                go = (uint32_t)((rowbase + x0 + 4 * k) * 4);
                cs = rowok ? 16u : 0u;
                sa = smem_u32(&sm[0][lz][ly][4 * k]);
            } else if (k == 2) {                 // right col x0+8 -> word 8
                bool ok = rowok && (x0 + 8 < W_);
                go = (uint32_t)((rowbase + min(x0 + 8, W_ - 1)) * 4);
                cs = ok ? 4u : 0u;
                sa = smem_u32(&sm[0][lz][ly][8]);
            } else {                             // left halo x0-1 -> hs[r]
                bool ok = rowok && (x0 >= 1);
                go = (uint32_t)((rowbase + max(x0 - 1, 0)) * 4);
                cs = ok ? 4u : 0u;
                sa = smem_u32(&hs[0][r]);
            }
            if (sl == 0) { sadr0 = sa; goff0 = go; csz0 = cs; }
            else         { sadr1 = sa; goff1 = go; csz1 = cs; }
        }
    }
    const uint32_t sstep = isMain ? (uint32_t)BUFBYTES : (uint32_t)HSBYTES;

    u64 acc[27];
#pragma unroll
    for (int o = 0; o < 27; o++) acc[o] = 0ull;

    const float* xp = xb + (size_t)(z0 + tz) * plane + (y0 + ty) * W_ + x0 + tx * TX;

    // ---- prologue: stage channels 0 and 1 ----
#pragma unroll
    for (int s = 0; s < STAGES - 1; s++) {
        const uint32_t cb = (uint32_t)s * volbytes;
        const uint32_t bo = (uint32_t)s * sstep;
        if (is16) {
            cp_async16(sadr0 + bo, ybc + (goff0 + cb), csz0);
            if (v1) cp_async16(sadr1 + bo, ybc + (goff1 + cb), csz1);
        } else {
            cp_async4(sadr0 + bo, ybc + (goff0 + cb), csz0);
            if (v1) cp_async4(sadr1 + bo, ybc + (goff1 + cb), csz1);
        }
        cp_commit();
    }

    float2 xv = *(const float2*)xp;
    int bu = 0, bu2 = 2;

    for (int c = 0; c < C_; c++) {
        if (c == C_ - 1) cp_wait<0>(); else cp_wait<1>();
        __syncthreads();

        // issue stage c+2 into buffer bu2
        if (c + 2 < C_) {
            const uint32_t cb = (uint32_t)(c + 2) * volbytes;
            const uint32_t bo = (uint32_t)bu2 * sstep;
            if (is16) {
                cp_async16(sadr0 + bo, ybc + (goff0 + cb), csz0);
                if (v1) cp_async16(sadr1 + bo, ybc + (goff1 + cb), csz1);
            } else {
                cp_async4(sadr0 + bo, ybc + (goff0 + cb), csz0);
                if (v1) cp_async4(sadr1 + bo, ybc + (goff1 + cb), csz1);
            }
            cp_commit();
        }

        // prefetch x for c+1 (covered by the FMA block)
        float2 xn;
        if (c + 1 < C_) xn = *(const float2*)(xp + (size_t)(c + 1) * vol);

        const u64 xa = packf2(xv.x, xv.y);
        const float (*smb)[SMY][SMXW] = sm[bu];
        const float* hsb = hs[bu];

#pragma unroll
        for (int dz = 0; dz < 3; dz++) {
#pragma unroll
            for (int dy = 0; dy < 3; dy++) {
                const int zp = tz + dz;
                const int ry = ty + dy;
                const float* row = &smb[zp][ry][0];
                const u64 a = *(const u64*)(row + 2 * tx);         // gmem (x0+2tx, x0+2tx+1)
                const float* m1p = (tx == 0) ? &hsb[zp * SMY + ry] : (row + 2 * tx - 1);
                const float m1 = *m1p;                             // gmem x0+2tx-1
                const float c2 = row[2 * tx + 2];                  // gmem x0+2tx+2
                const float2 fa = unpackf2(a);
                const u64 pm10 = packf2(m1, fa.x);
                const u64 p12  = packf2(fa.y, c2);
                const int o = (dz * 3 + dy) * 3;
                ffma2(acc[o + 0], xa, pm10);
                ffma2(acc[o + 1], xa, a);
                ffma2(acc[o + 2], xa, p12);
            }
        }

        if (c + 1 < C_) xv = xn;
        bu  = (bu  == STAGES - 1) ? 0 : bu + 1;
        bu2 = (bu2 == STAGES - 1) ? 0 : bu2 + 1;
    }

    // ---- epilogue: scale + streaming stores ----
    const float scale = 0.125f;
    const size_t sp = (size_t)(z0 + tz) * plane + (size_t)(y0 + ty) * W_ + (x0 + tx * TX);
    float* outb = out + (size_t)b * 27 * vol + sp;
#pragma unroll
    for (int off = 0; off < 27; off++) {
        float2 a = unpackf2(acc[off]);
        float2 o;
        o.x = a.x * scale;
        o.y = a.y * scale;
        __stcs((float2*)(outb + (size_t)off * vol), o);
    }
}

extern "C" void kernel_launch(void* const* d_in, const int* in_sizes, int n_in,
                              void* d_out, int out_size)
{
    const float* x = (const float*)d_in[0];
    const float* y = (const float*)d_in[1];
    float* out = (float*)d_out;

    const int nblocks = B_ * (D_ / TZ) * (H_ / TY) * (W_ / TXB); // 4000
    wincorr_kernel<<<nblocks, NTH>>>(x, y, out);
}

// round 15
// speedup vs baseline: 1.0259x; 1.0259x over previous
#include <cuda_runtime.h>
#include <cstdint>

// WinCorr: corr[b,off,z,y,x] = (1/8) * sum_c x[b,c,z,y,x] * y[b,c,z+dz-1,y+dy-1,x+dx-1]
// x,y = (2,64,80,80,80) f32 ; out = (2,27,80,80,80) f32
// R15: aligned smem (word m <-> gmem col x0+m), warp-uniform 16B staging (10 LDGSTS ops/ch),
//      dx=-1 accumulators shifted to outputs 4tx+1..4tx+4 so compute stays 2 LDS/row.
//      td=dz split, TX=4, tile 4x8x16, 384 threads, 3-stage wait<1> pipeline.

#define B_  2
#define C_  64
#define D_  80
#define H_  80
#define W_  80

#define TZ  4
#define TY  8
#define TXB 16
#define NTH 384          // tx(4) * ty(8) * tz(4) * td(3)

#define SMZ 6
#define SMY 10
#define SMXW 48          // word stride; 48 mod 32 = 16 -> conflict-free LDS.128/LDS.64 phases
#define STAGES 3
#define BUFBYTES (SMZ*SMY*SMXW*4)    // 11520 ; x3 = 34560
#define NROWS (SMZ*SMY)              // 60
#define N16 (NROWS*4)                // 240 16B slots (words 0..15 <-> cols x0..x0+15)
#define N4BASE 256                   // 4B slots: tids 256..315 -> word 16 (col x0+16)

typedef unsigned long long u64;

__device__ __forceinline__ uint32_t smem_u32(const void* p) {
    return (uint32_t)__cvta_generic_to_shared(p);
}
__device__ __forceinline__ void cp_async16(uint32_t saddr, const void* gaddr, uint32_t srcsz) {
    asm volatile("cp.async.cg.shared.global [%0], [%1], 16, %2;\n"
                 :: "r"(saddr), "l"(gaddr), "r"(srcsz) : "memory");
}
__device__ __forceinline__ void cp_async4(uint32_t saddr, const void* gaddr, uint32_t srcsz) {
    asm volatile("cp.async.ca.shared.global [%0], [%1], 4, %2;\n"
                 :: "r"(saddr), "l"(gaddr), "r"(srcsz) : "memory");
}
__device__ __forceinline__ void cp_commit() {
    asm volatile("cp.async.commit_group;\n" ::: "memory");
}
template<int N> __device__ __forceinline__ void cp_wait() {
    asm volatile("cp.async.wait_group %0;\n" :: "n"(N) : "memory");
}
__device__ __forceinline__ void ffma2(u64& acc, u64 a, u64 b) {
    asm("fma.rn.f32x2 %0, %1, %2, %0;" : "+l"(acc) : "l"(a), "l"(b));
}
__device__ __forceinline__ u64 packf2(float lo, float hi) {
    u64 r; asm("mov.b64 %0, {%1, %2};" : "=l"(r) : "f"(lo), "f"(hi)); return r;
}
__device__ __forceinline__ float2 unpackf2(u64 v) {
    float2 r; asm("mov.b64 {%0, %1}, %2;" : "=f"(r.x), "=f"(r.y) : "l"(v)); return r;
}

__global__ void __launch_bounds__(NTH, 2)
wincorr_kernel(const float* __restrict__ x,
               const float* __restrict__ y,
               float* __restrict__ out)
{
    // ---- decode block -> (b, z0, y0, x0) ----
    int bid = blockIdx.x;
    int bx = bid % (W_ / TXB); bid /= (W_ / TXB);   // 5
    int by = bid % (H_ / TY);  bid /= (H_ / TY);    // 10
    int bz = bid % (D_ / TZ);  bid /= (D_ / TZ);    // 20
    int b  = bid;
    const int z0 = bz * TZ, y0 = by * TY, x0 = bx * TXB;

    const int tid = threadIdx.x;
    const int tx = tid & 3;
    const int ty = (tid >> 2) & 7;
    const int tz = (tid >> 5) & 3;
    const int td = tid >> 7;         // dz slice 0..2 (warp-uniform)

    __shared__ __align__(16) float sm[STAGES][SMZ][SMY][SMXW];

    const int plane = H_ * W_;       // 6400
    const int vol   = D_ * plane;    // 512000
    const uint32_t volbytes = (uint32_t)vol * 4u;

    const float* xb = x + (size_t)b * C_ * vol;
    const float* yb = y + (size_t)b * C_ * vol;
    const char*  ybc = (const char*)yb;

    // ---- one staging slot per thread; warp-uniform kind ----
    // tids 0..239: 16B chunk (slot s: row s>>2, chunk k=s&3 -> words 4k, cols x0+4k..+3)
    // tids 256..315: 4B (row tid-256, word 16, col x0+16)
    const bool stg16 = (tid < N16);
    const bool stg4  = (tid >= N4BASE) && (tid < N4BASE + NROWS);
    uint32_t sadr = 0, goff = 0, csz = 0;
    {
        int r, wofs, gcol;
        bool colok;
        if (stg16) {
            r = tid >> 2;
            int k = tid & 3;
            wofs = 4 * k;
            gcol = x0 + 4 * k;       // 16B aligned; cols x0..x0+15 always < W
            colok = true;
        } else {
            r = stg4 ? (tid - N4BASE) : 0;
            wofs = 16;
            gcol = x0 + 16;
            colok = (gcol < W_);
        }
        int lz = r / SMY;
        int ly = r - lz * SMY;
        int gz = z0 - 1 + lz, gy = y0 - 1 + ly;
        bool rowok = ((unsigned)gz < (unsigned)D_) && ((unsigned)gy < (unsigned)H_);
        int cz = min(max(gz, 0), D_ - 1);
        int cy = min(max(gy, 0), H_ - 1);
        goff = (uint32_t)((cz * plane + cy * W_ + min(gcol, W_ - 4)) * 4);
        csz  = (rowok && colok) ? (stg16 ? 16u : 4u) : 0u;
        sadr = smem_u32(&sm[0][lz][ly][wofs]);
    }

    // accumulators: per dy (0..2): dx=-1 (outputs 4tx+1..4tx+4), dx=0, dx=+1 (outputs 4tx..4tx+3)
    u64 m1l[3], m1h[3], z0l[3], z0h[3], p1l[3], p1h[3];
#pragma unroll
    for (int o = 0; o < 3; o++) {
        m1l[o] = 0ull; m1h[o] = 0ull;
        z0l[o] = 0ull; z0h[o] = 0ull;
        p1l[o] = 0ull; p1h[o] = 0ull;
    }

    const float* xp = xb + (size_t)(z0 + tz) * plane + (y0 + ty) * W_ + x0 + 4 * tx;
    const bool x4ok = (x0 + 4 * tx + 4) < W_;   // only false for bx=4, tx=3
    const int zp = tz + td;          // smem z-plane this thread reads

    // ---- prologue: stage channels 0 and 1 ----
#pragma unroll
    for (int s = 0; s < STAGES - 1; s++) {
        const uint32_t cb = (uint32_t)s * volbytes;
        const uint32_t bo = (uint32_t)s * BUFBYTES;
        if (stg16) cp_async16(sadr + bo, ybc + (goff + cb), csz);
        else if (stg4) cp_async4(sadr + bo, ybc + (goff + cb), csz);
        cp_commit();
    }

    float4 xv = *(const float4*)xp;
    float x4 = x4ok ? xp[4] : 0.f;
    int bu = 0, bu2 = 2;

    for (int c = 0; c < C_; c++) {
        if (c == C_ - 1) cp_wait<0>(); else cp_wait<1>();
        __syncthreads();

        // issue stage c+2 into buffer bu2
        if (c + 2 < C_) {
            const uint32_t cb = (uint32_t)(c + 2) * volbytes;
            const uint32_t bo = (uint32_t)bu2 * BUFBYTES;
            if (stg16) cp_async16(sadr + bo, ybc + (goff + cb), csz);
            else if (stg4) cp_async4(sadr + bo, ybc + (goff + cb), csz);
            cp_commit();
        }

        // prefetch x for c+1 (covered by the FMA block)
        float4 xn; float x4n;
        if (c + 1 < C_) {
            xn = *(const float4*)(xp + (size_t)(c + 1) * vol);
            x4n = x4ok ? xp[(size_t)(c + 1) * vol + 4] : 0.f;
        }

        const u64 xa01 = packf2(xv.x, xv.y);   // x[0],x[1]
        const u64 xa23 = packf2(xv.z, xv.w);   // x[2],x[3]
        const u64 xb12 = packf2(xv.y, xv.z);   // x[1],x[2]
        const u64 xb34 = packf2(xv.w, x4);     // x[3],x[4]
        const float (*smb)[SMY][SMXW] = sm[bu];

#pragma unroll
        for (int dy = 0; dy < 3; dy++) {
            const float* row = &smb[zp][ty + dy][4 * tx];
            const ulonglong2 Q = *(const ulonglong2*)row;   // (c0,c1),(c2,c3)  LDS.128
            const u64 T = *(const u64*)(row + 4);           // (c4,c5*)         LDS.64
            const float2 f01 = unpackf2(Q.x);
            const float2 f23 = unpackf2(Q.y);
            const float2 f45 = unpackf2(T);
            const u64 p12 = packf2(f01.y, f23.x);           // (c1,c2)
            const u64 p34 = packf2(f23.y, f45.x);           // (c3,c4)
            // dx=-1: outputs 4tx+1..4tx+4 use cols 4tx..4tx+3 (= Q) with shifted x
            ffma2(m1l[dy], xb12, Q.x);
            ffma2(m1h[dy], xb34, Q.y);
            // dx=0: outputs 4tx..4tx+3 use cols 4tx..4tx+3
            ffma2(z0l[dy], xa01, Q.x);
            ffma2(z0h[dy], xa23, Q.y);
            // dx=+1: outputs 4tx..4tx+3 use cols 4tx+1..4tx+4
            ffma2(p1l[dy], xa01, p12);
            ffma2(p1h[dy], xa23, p34);
        }

        if (c + 1 < C_) { xv = xn; x4 = x4n; }
        bu  = (bu  == STAGES - 1) ? 0 : bu + 1;
        bu2 = (bu2 == STAGES - 1) ? 0 : bu2 + 1;
    }

    // ---- epilogue: scale + stores (off = td*9 + dy*3 + dxi; dxi 0/1/2 = dx -1/0/+1) ----
    const float scale = 0.125f;
    const size_t sp = (size_t)(z0 + tz) * plane + (size_t)(y0 + ty) * W_ + x0;
    float* outb = out + (size_t)b * 27 * vol + sp;
#pragma unroll
    for (int dy = 0; dy < 3; dy++) {
        const int offbase = td * 9 + dy * 3;
        // dxi=1 (dx=0): aligned float4 at x0+4tx
        {
            float2 lo = unpackf2(z0l[dy]);
            float2 hi = unpackf2(z0h[dy]);
            float4 v = { lo.x * scale, lo.y * scale, hi.x * scale, hi.y * scale };
            __stcs((float4*)(outb + (size_t)(offbase + 1) * vol + 4 * tx), v);
        }
        // dxi=2 (dx=+1): aligned float4 at x0+4tx
        {
            float2 lo = unpackf2(p1l[dy]);
            float2 hi = unpackf2(p1h[dy]);
            float4 v = { lo.x * scale, lo.y * scale, hi.x * scale, hi.y * scale };
            __stcs((float4*)(outb + (size_t)(offbase + 2) * vol + 4 * tx), v);
        }
        // dxi=0 (dx=-1): outputs at x0+4tx+1..x0+4tx+4 (scalar stores)
        {
            float* o0 = outb + (size_t)offbase * vol + 4 * tx + 1;
            float2 lo = unpackf2(m1l[dy]);
            float2 hi = unpackf2(m1h[dy]);
            __stcs(o0 + 0, lo.x * scale);
            __stcs(o0 + 1, lo.y * scale);
            __stcs(o0 + 2, hi.x * scale);
            if (x4ok) __stcs(o0 + 3, hi.y * scale);   // col x0+4tx+4 (skip col 80)
            // col 0 for dx=-1 is exactly zero (y zero-padding): store it once at bx==0
            if (bx == 0 && tx == 0) __stcs(outb + (size_t)offbase * vol, 0.f);
        }
    }
}

extern "C" void kernel_launch(void* const* d_in, const int* in_sizes, int n_in,
                              void* d_out, int out_size)
{
    const float* x = (const float*)d_in[0];
    const float* y = (const float*)d_in[1];
    float* out = (float*)d_out;

    const int nblocks = B_ * (D_ / TZ) * (H_ / TY) * (W_ / TXB); // 2000
    wincorr_kernel<<<nblocks, NTH>>>(x, y, out);
}